// round 2
// baseline (speedup 1.0000x reference)
#include <cuda_runtime.h>

// Problem constants (fixed by setup_inputs)
#define B_    2
#define N_    512
#define E_    768
#define H_    48
#define D_    16
#define NEXP_ 256
#define M_    768   // N_ + NEXP_

// ---------------- device scratch (no allocations allowed) ----------------
__device__ float g_Q[B_*N_*E_];        // scaled Q projection, [b*N+n][e]
__device__ float g_K[B_*N_*E_];        // K projection, [b*N+n][e]
__device__ float g_VW[B_*N_*H_];       // vw[b,n,h] = v . w_force per head
__device__ float g_Wveff[H_*E_];       // folded Wv * w_force
__device__ float g_beff[H_];
__device__ float g_part[12*B_*N_*3];   // per-headgroup partial forces

// ---------------- kernel 1: fold Wv with w_force ----------------
__global__ void wveff_kernel(const float* __restrict__ Wv,
                             const float* __restrict__ bv,
                             const float* __restrict__ wf)
{
    int h = blockIdx.x, e = threadIdx.x;
    float sv = 0.f;
#pragma unroll
    for (int dd = 0; dd < 16; dd++)
        sv = fmaf(wf[h*16+dd], Wv[(h*16+dd)*E_ + e], sv);
    g_Wveff[h*E_ + e] = sv;
    if (e == 0) {
        float bb = 0.f;
#pragma unroll
        for (int dd = 0; dd < 16; dd++)
            bb = fmaf(wf[h*16+dd], bv[h*16+dd], bb);
        g_beff[h] = bb;
    }
}

// ---------------- kernel 2: fused Q+K projection GEMM ----------------
// C[i,j] = sum_k A[i,k]*W[j,k] + bias[j]   (Q gets *0.25 scaling)
// M=1024 rows, Ncols=1536 (Wq | Wk).  64x64 tile, 64 threads, 8x8 microtile.
__global__ __launch_bounds__(64) void qk_gemm(
    const float* __restrict__ A,
    const float* __restrict__ Wq, const float* __restrict__ bq,
    const float* __restrict__ Wk, const float* __restrict__ bk)
{
    __shared__ float As[16][68];
    __shared__ float Bs[16][68];
    int t  = threadIdx.x;
    int tx = t & 7, ty = t >> 3;
    int row0 = blockIdx.y * 64;
    int col0 = blockIdx.x * 64;

    const float* __restrict__ W; const float* __restrict__ bvec;
    float scale; float* C; int cb;
    if (col0 < E_) { W = Wq; bvec = bq; scale = 0.25f; C = g_Q; cb = col0; }
    else           { W = Wk; bvec = bk; scale = 1.0f;  C = g_K; cb = col0 - E_; }

    float acc[8][8];
#pragma unroll
    for (int ii = 0; ii < 8; ii++)
#pragma unroll
        for (int jj = 0; jj < 8; jj++) acc[ii][jj] = 0.f;

#pragma unroll 3
    for (int k0 = 0; k0 < E_; k0 += 16) {
#pragma unroll
        for (int r = 0; r < 4; r++) {
            int i  = r*16 + (t >> 2);
            int k4 = (t & 3) * 4;
            float4 va = *(const float4*)(A + (row0+i)*E_ + k0 + k4);
            As[k4+0][i] = va.x; As[k4+1][i] = va.y; As[k4+2][i] = va.z; As[k4+3][i] = va.w;
            float4 vb = *(const float4*)(W + (cb+i)*E_ + k0 + k4);
            Bs[k4+0][i] = vb.x; Bs[k4+1][i] = vb.y; Bs[k4+2][i] = vb.z; Bs[k4+3][i] = vb.w;
        }
        __syncthreads();
#pragma unroll
        for (int k = 0; k < 16; k++) {
            float a[8], bb[8];
            *(float4*)&a[0]  = *(const float4*)&As[k][ty*8];
            *(float4*)&a[4]  = *(const float4*)&As[k][ty*8+4];
            *(float4*)&bb[0] = *(const float4*)&Bs[k][tx*8];
            *(float4*)&bb[4] = *(const float4*)&Bs[k][tx*8+4];
#pragma unroll
            for (int ii = 0; ii < 8; ii++)
#pragma unroll
                for (int jj = 0; jj < 8; jj++)
                    acc[ii][jj] = fmaf(a[ii], bb[jj], acc[ii][jj]);
        }
        __syncthreads();
    }

    float bcol[8];
#pragma unroll
    for (int jj = 0; jj < 8; jj++) bcol[jj] = bvec[cb + tx*8 + jj];
#pragma unroll
    for (int ii = 0; ii < 8; ii++) {
        int gr = row0 + ty*8 + ii;
#pragma unroll
        for (int jj = 0; jj < 8; jj++)
            C[gr*E_ + cb + tx*8 + jj] = scale * (acc[ii][jj] + bcol[jj]);
    }
}

// ---------------- kernel 3: vw = query @ Wv_eff^T + b_eff ----------------
__global__ __launch_bounds__(768) void vw_kernel(const float* __restrict__ query)
{
    __shared__ float qrow[E_];
    int row = blockIdx.x;                      // b*N + n
    qrow[threadIdx.x] = query[row*E_ + threadIdx.x];
    __syncthreads();
    int h = threadIdx.x >> 4, lane = threadIdx.x & 15;
    const float* __restrict__ wv = &g_Wveff[h*E_];
    float sacc = 0.f;
#pragma unroll 8
    for (int j = lane; j < E_; j += 16) sacc = fmaf(qrow[j], wv[j], sacc);
#pragma unroll
    for (int o = 8; o > 0; o >>= 1) sacc += __shfl_down_sync(0xffffffffu, sacc, o, 16);
    if (lane == 0) g_VW[row*H_ + h] = sacc + g_beff[h];
}

// ---------------- kernel 4: fused attention + force contraction ----------------
// grid (12 head-groups of 4, 16 n-tiles of 32, B).  128 threads:
//   t -> h = t&3 (head in group), nq = (t>>2)&7 (n-quad), s = t>>5 (m-quarter)
// Each thread: online softmax over its quarter of m for 4 n-rows of 1 head.
__global__ __launch_bounds__(128) void attn_kernel(
    const float* __restrict__ bias, const float* __restrict__ dp,
    const int*   __restrict__ outcell)
{
    constexpr int HG = 4, NT = 32, MC = 16;
    __shared__ float sK[MC][4][HG][4];     // [mc][d4][h][4] -> conflict-free LDS.128
    __shared__ float sBias[HG][33][17];    // padded: 32 distinct banks across (nq,h)
    __shared__ float sDP[3][33][17];
    __shared__ float sVW[MC][HG];
    __shared__ float scomb[NT][HG][4][5];

    int t  = threadIdx.x;
    int h  = t & 3;
    int nq = (t >> 2) & 7;
    int s  = t >> 5;
    int g  = blockIdx.x;
    int h0 = g * HG;
    int n0 = blockIdx.y * NT;
    int b  = blockIdx.z;
    const int* __restrict__ oc = outcell + b*NEXP_;

    // Q fragment in registers: 4 n-rows x 16 dims of head h0+h (invariant over m)
    float qreg[4][16];
#pragma unroll
    for (int i = 0; i < 4; i++) {
        const float* qb = &g_Q[(b*N_ + n0 + nq*4 + i)*E_ + (h0+h)*D_];
#pragma unroll
        for (int d4 = 0; d4 < 4; d4++) {
            float4 v = *(const float4*)(qb + d4*4);
            qreg[i][d4*4+0] = v.x; qreg[i][d4*4+1] = v.y;
            qreg[i][d4*4+2] = v.z; qreg[i][d4*4+3] = v.w;
        }
    }

    float mx[4], den[4], A0[4], A1[4], A2[4];
#pragma unroll
    for (int i = 0; i < 4; i++) { mx[i] = -1e30f; den[i] = 0.f; A0[i] = A1[i] = A2[i] = 0.f; }

#pragma unroll 1
    for (int ch = 0; ch < M_/MC; ch++) {
        int m0 = ch * MC;
        __syncthreads();
        // --- stage K (gathered rows), 256 float4 by 128 threads ---
#pragma unroll
        for (int it = 0; it < 2; it++) {
            int idx = it*128 + t;
            int mc = idx >> 4, q4 = idx & 15;
            int m = m0 + mc;
            int r = (m < N_) ? m : oc[m - N_];
            float4 v = *(const float4*)&g_K[(b*N_ + r)*E_ + h0*D_ + q4*4];
            int hl = q4 >> 2, d4 = q4 & 3;
            *(float4*)&sK[mc][d4][hl][0] = v;
        }
        // --- stage bias (coalesced over m) ---
        {
            int bb = b*H_ + h0;
#pragma unroll
            for (int it = 0; it < 16; it++) {
                int idx = it*128 + t;
                int mc = idx & 15, n = (idx >> 4) & 31, hh = idx >> 9;
                sBias[hh][n][mc] = bias[(bb+hh)*(N_*M_) + (n0+n)*M_ + m0 + mc];
            }
        }
        // --- stage delta_pos ---
#pragma unroll
        for (int it = 0; it < 12; it++) {
            int idx = it*128 + t;
            int n = idx / 48; int rem = idx - n*48;
            int mc = rem / 3; int c = rem - mc*3;
            sDP[c][n][mc] = dp[((b*N_ + n0+n)*M_ + m0+mc)*3 + c];
        }
        // --- stage vw (gathered) ---
        if (t < MC*HG) {
            int mc = t >> 2, hh = t & 3;
            int m = m0 + mc;
            int r = (m < N_) ? m : oc[m - N_];
            sVW[mc][hh] = g_VW[(b*N_ + r)*H_ + h0 + hh];
        }
        __syncthreads();

        // --- compute: this thread's 4 m-columns x 4 n-rows ---
#pragma unroll
        for (int jj = 0; jj < 4; jj++) {
            int mc = s*4 + jj;
            float kk[16];
#pragma unroll
            for (int d4 = 0; d4 < 4; d4++) {
                float4 v = *(const float4*)&sK[mc][d4][h][0];
                kk[d4*4+0] = v.x; kk[d4*4+1] = v.y;
                kk[d4*4+2] = v.z; kk[d4*4+3] = v.w;
            }
            float vwv = sVW[mc][h];
#pragma unroll
            for (int i = 0; i < 4; i++) {
                int n = nq*4 + i;
                float l = sBias[h][n][mc];
#pragma unroll
                for (int d = 0; d < 16; d++) l = fmaf(qreg[i][d], kk[d], l);
                float mOld = mx[i];
                float mNew = fmaxf(mOld, l);
                float corr = __expf(mOld - mNew);
                float p    = __expf(l - mNew);
                den[i] = den[i]*corr + p;
                float pv = p * vwv;
                A0[i] = A0[i]*corr + pv * sDP[0][n][mc];
                A1[i] = A1[i]*corr + pv * sDP[1][n][mc];
                A2[i] = A2[i]*corr + pv * sDP[2][n][mc];
                mx[i] = mNew;
            }
        }
    }

    __syncthreads();
#pragma unroll
    for (int i = 0; i < 4; i++) {
        int n = nq*4 + i;
        scomb[n][h][s][0] = mx[i];  scomb[n][h][s][1] = den[i];
        scomb[n][h][s][2] = A0[i];  scomb[n][h][s][3] = A1[i];  scomb[n][h][s][4] = A2[i];
    }
    __syncthreads();

    if (t < NT) {
        int n = t;
        float f0 = 0.f, f1 = 0.f, f2 = 0.f;
#pragma unroll
        for (int hh = 0; hh < HG; hh++) {
            float Mv = -1e30f;
#pragma unroll
            for (int ss = 0; ss < 4; ss++) Mv = fmaxf(Mv, scomb[n][hh][ss][0]);
            float dn = 0.f, a0 = 0.f, a1 = 0.f, a2 = 0.f;
#pragma unroll
            for (int ss = 0; ss < 4; ss++) {
                float w = __expf(scomb[n][hh][ss][0] - Mv);
                dn += scomb[n][hh][ss][1] * w;
                a0 += scomb[n][hh][ss][2] * w;
                a1 += scomb[n][hh][ss][3] * w;
                a2 += scomb[n][hh][ss][4] * w;
            }
            float inv = 1.0f / dn;
            f0 = fmaf(a0, inv, f0); f1 = fmaf(a1, inv, f1); f2 = fmaf(a2, inv, f2);
        }
        float* o = &g_part[((g*B_ + b)*N_ + n0 + n)*3];
        o[0] = f0; o[1] = f1; o[2] = f2;
    }
}

// ---------------- kernel 5: sum head-group partials ----------------
__global__ void reduce_kernel(float* __restrict__ out)
{
    int i = blockIdx.x*1024 + threadIdx.x;   // 3 blocks * 1024 = 3072
    float sv = 0.f;
#pragma unroll
    for (int gi = 0; gi < 12; gi++) sv += g_part[gi*(B_*N_*3) + i];
    out[i] = sv;
}

// ---------------- launch ----------------
extern "C" void kernel_launch(void* const* d_in, const int* in_sizes, int n_in,
                              void* d_out, int out_size)
{
    const float* query = (const float*)d_in[0];
    const float* bias  = (const float*)d_in[1];
    const float* dp    = (const float*)d_in[2];
    const int*   oc    = (const int*)  d_in[3];
    const float* Wq    = (const float*)d_in[4];
    const float* bq    = (const float*)d_in[5];
    const float* Wk    = (const float*)d_in[6];
    const float* bk    = (const float*)d_in[7];
    const float* Wv    = (const float*)d_in[8];
    const float* bv    = (const float*)d_in[9];
    const float* wf    = (const float*)d_in[10];
    float* out = (float*)d_out;

    wveff_kernel<<<H_, E_>>>(Wv, bv, wf);
    qk_gemm<<<dim3(24, 16), 64>>>(query, Wq, bq, Wk, bk);
    vw_kernel<<<B_*N_, E_>>>(query);
    attn_kernel<<<dim3(12, 16, 2), 128>>>(bias, dp, oc);
    reduce_kernel<<<3, 1024>>>(out);
}

// round 4
// speedup vs baseline: 1.4357x; 1.4357x over previous
#include <cuda_runtime.h>

#define B_    2
#define N_    512
#define E_    768
#define H_    48
#define D_    16
#define NEXP_ 256
#define M_    768
#define LOG2E 1.4426950408889634f

typedef unsigned long long ull;

__device__ __forceinline__ ull pk2(float lo, float hi){ ull r; asm("mov.b64 %0,{%1,%2};":"=l"(r):"f"(lo),"f"(hi)); return r; }
__device__ __forceinline__ void upk2(float&lo,float&hi,ull v){ asm("mov.b64 {%0,%1},%2;":"=f"(lo),"=f"(hi):"l"(v)); }
__device__ __forceinline__ ull fma2_(ull a, ull b, ull c){ ull d; asm("fma.rn.f32x2 %0,%1,%2,%3;":"=l"(d):"l"(a),"l"(b),"l"(c)); return d; }
__device__ __forceinline__ ull add2_(ull a, ull b){ ull d; asm("add.rn.f32x2 %0,%1,%2;":"=l"(d):"l"(a),"l"(b)); return d; }
__device__ __forceinline__ ull mul2_(ull a, ull b){ ull d; asm("mul.rn.f32x2 %0,%1,%2;":"=l"(d):"l"(a),"l"(b)); return d; }
__device__ __forceinline__ float ex2_(float x){ float r; asm("ex2.approx.f32 %0,%1;":"=f"(r):"f"(x)); return r; }

// ---------------- device scratch ----------------
__device__ float g_Q[B_*N_*E_];          // Q proj, pre-scaled by 0.25*log2e
__device__ float g_K[B_*N_*E_];          // K proj
__device__ float g_VW[B_*N_*H_];         // v . w_force per head
__device__ float g_Wveff[H_*E_];
__device__ float g_beff[H_];
__device__ float g_part[12*2*B_*N_*16];  // [g][ms][b][n][hh][4]: den,A0,A1,A2

// ---------------- kernel 1: fold Wv with w_force ----------------
__global__ void wveff_kernel(const float* __restrict__ Wv,
                             const float* __restrict__ bv,
                             const float* __restrict__ wf)
{
    int h = blockIdx.x, e = threadIdx.x;
    float sv = 0.f;
#pragma unroll
    for (int dd = 0; dd < 16; dd++)
        sv = fmaf(wf[h*16+dd], Wv[(h*16+dd)*E_ + e], sv);
    g_Wveff[h*E_ + e] = sv;
    if (e == 0) {
        float bb = 0.f;
#pragma unroll
        for (int dd = 0; dd < 16; dd++)
            bb = fmaf(wf[h*16+dd], bv[h*16+dd], bb);
        g_beff[h] = bb;
    }
}

// ---------------- kernel 2: fused Q+K projection GEMM (f32x2) ----------------
// 64x64 tile, 128 threads, micro 4 rows x 8 cols (4 col-pairs as f32x2).
__global__ __launch_bounds__(128) void qk_gemm(
    const float* __restrict__ A,
    const float* __restrict__ Wq, const float* __restrict__ bq,
    const float* __restrict__ Wk, const float* __restrict__ bk)
{
    __shared__ ull   Asd[16*64];   // [k][row] duplicated (a,a)
    __shared__ float Bs[16*68];    // [k][col] padded

    int t  = threadIdx.x;
    int tx = t & 7, ty = t >> 3;          // tx: col group (8 cols), ty: row group (4 rows)
    int row0 = blockIdx.y * 64;
    int col0 = blockIdx.x * 64;

    const float* __restrict__ W; const float* __restrict__ bvec;
    float scale; float* C; int cb;
    if (col0 < E_) { W = Wq; bvec = bq; scale = 0.25f*LOG2E; C = g_Q; cb = col0; }
    else           { W = Wk; bvec = bk; scale = 1.0f;        C = g_K; cb = col0 - E_; }

    ull acc[4][4];
#pragma unroll
    for (int r = 0; r < 4; r++)
#pragma unroll
        for (int j = 0; j < 4; j++) acc[r][j] = 0ull;

    for (int k0 = 0; k0 < E_; k0 += 16) {
#pragma unroll
        for (int it = 0; it < 2; it++) {
            int idx = it*128 + t;
            int row = idx >> 2;         // 0..63
            int kq  = (idx & 3) * 4;    // k sub-offset
            float4 va = *(const float4*)(A + (row0+row)*E_ + k0 + kq);
            Asd[(kq+0)*64+row] = pk2(va.x, va.x);
            Asd[(kq+1)*64+row] = pk2(va.y, va.y);
            Asd[(kq+2)*64+row] = pk2(va.z, va.z);
            Asd[(kq+3)*64+row] = pk2(va.w, va.w);
            float4 vb = *(const float4*)(W + (cb+row)*E_ + k0 + kq);
            Bs[(kq+0)*68+row] = vb.x;
            Bs[(kq+1)*68+row] = vb.y;
            Bs[(kq+2)*68+row] = vb.z;
            Bs[(kq+3)*68+row] = vb.w;
        }
        __syncthreads();
#pragma unroll
        for (int k = 0; k < 16; k++) {
            ull a2[4];
#pragma unroll
            for (int r = 0; r < 4; r++) a2[r] = Asd[k*64 + ty*4 + r];
            const ull* bp = (const ull*)&Bs[k*68 + tx*8];
            ull b2[4];
            b2[0] = bp[0]; b2[1] = bp[1]; b2[2] = bp[2]; b2[3] = bp[3];
#pragma unroll
            for (int r = 0; r < 4; r++)
#pragma unroll
                for (int j = 0; j < 4; j++)
                    acc[r][j] = fma2_(a2[r], b2[j], acc[r][j]);
        }
        __syncthreads();
    }

    float bc[8];
#pragma unroll
    for (int j = 0; j < 8; j++) bc[j] = bvec[cb + tx*8 + j];
#pragma unroll
    for (int r = 0; r < 4; r++) {
        float* Cr = C + (row0 + ty*4 + r)*E_ + cb + tx*8;
        float4 o;
        float c0,c1;
        upk2(c0,c1,acc[r][0]); o.x = scale*(c0+bc[0]); o.y = scale*(c1+bc[1]);
        upk2(c0,c1,acc[r][1]); o.z = scale*(c0+bc[2]); o.w = scale*(c1+bc[3]);
        *(float4*)Cr = o;
        upk2(c0,c1,acc[r][2]); o.x = scale*(c0+bc[4]); o.y = scale*(c1+bc[5]);
        upk2(c0,c1,acc[r][3]); o.z = scale*(c0+bc[6]); o.w = scale*(c1+bc[7]);
        *(float4*)(Cr+4) = o;
    }
}

// ---------------- kernel 3: vw = query @ Wv_eff^T + b_eff ----------------
__global__ __launch_bounds__(768) void vw_kernel(const float* __restrict__ query)
{
    __shared__ float qrow[E_];
    int row = blockIdx.x;
    qrow[threadIdx.x] = query[row*E_ + threadIdx.x];
    __syncthreads();
    int h = threadIdx.x >> 4, lane = threadIdx.x & 15;
    const float* __restrict__ wv = &g_Wveff[h*E_];
    float sacc = 0.f;
#pragma unroll 8
    for (int j = lane; j < E_; j += 16) sacc = fmaf(qrow[j], wv[j], sacc);
#pragma unroll
    for (int o = 8; o > 0; o >>= 1) sacc += __shfl_down_sync(0xffffffffu, sacc, o, 16);
    if (lane == 0) g_VW[row*H_ + h] = sacc + g_beff[h];
}

// ---------------- kernel 4: fused attention (no-max softmax, f32x2) ----------------
// grid (12 hg, 16 ntile, b*2+ms).  128 threads: h=t&3, nq=(t>>2)&7, s=t>>5.
// Thread: 4 n-rows (2 packed row-pairs) x 4 m-cols per 16-chunk; 24 chunks (m-half).
__global__ __launch_bounds__(128) void attn_kernel(
    const float* __restrict__ bias, const float* __restrict__ dp,
    const int*   __restrict__ outcell)
{
    __shared__ ulonglong2 sKraw[4*130];        // h stride 260 ull (banks 0/8/16/24)
    __shared__ float  sB[4*529];               // h*529 + mc*33 + n : 32 distinct banks
    __shared__ float  sDPs[3*528];             // c*528 + mc*33 + n
    __shared__ ull    sVW[16*4];               // mc*4+h, duplicated
    __shared__ float2 scomb[4][4][16][4];      // [s][h][rowpair][val]

    ull* sK = (ull*)sKraw;

    int t  = threadIdx.x;
    int h  = t & 3;
    int nq = (t >> 2) & 7;
    int s  = t >> 5;
    int g  = blockIdx.x;
    int h0 = g * 4;
    int n0 = blockIdx.y * 32;
    int bz = blockIdx.z;
    int b  = bz >> 1, ms = bz & 1;
    const int* __restrict__ oc = outcell + b*NEXP_;

    // Q row-pairs, packed (row r, row r+1), invariant over m. Already *0.25*log2e.
    ull qpk[2][16];
#pragma unroll
    for (int rp = 0; rp < 2; rp++) {
        const float* q0 = &g_Q[(b*N_ + n0 + nq*4 + rp*2)*E_ + (h0+h)*D_];
        const float* q1 = q0 + E_;
#pragma unroll
        for (int d = 0; d < 16; d++) qpk[rp][d] = pk2(q0[d], q1[d]);
    }

    ull den[2] = {0ull, 0ull};
    ull Ac[2][3] = {{0ull,0ull,0ull},{0ull,0ull,0ull}};

#pragma unroll 1
    for (int ch = 0; ch < 24; ch++) {
        int m0 = ms*384 + ch*16;
        __syncthreads();
        // --- K (gathered, stored duplicated) ---
#pragma unroll
        for (int it = 0; it < 2; it++) {
            int idx = it*128 + t;
            int mc = idx >> 4, q4 = idx & 15;
            int hh = q4 >> 2, dg = (q4 & 3)*4;
            int m = m0 + mc;
            int r = (m < N_) ? m : oc[m - N_];
            float4 v = *(const float4*)&g_K[(b*N_ + r)*E_ + (h0+hh)*D_ + dg];
            ull* dst = &sK[hh*260 + mc*16 + dg];
            dst[0] = pk2(v.x,v.x); dst[1] = pk2(v.y,v.y);
            dst[2] = pk2(v.z,v.z); dst[3] = pk2(v.w,v.w);
        }
        // --- bias (scaled by log2e at stage time) ---
        {
            int bb = b*H_ + h0;
#pragma unroll
            for (int it = 0; it < 16; it++) {
                int idx = it*128 + t;
                int mc = idx & 15, n = (idx >> 4) & 31, hh = idx >> 9;
                sB[hh*529 + mc*33 + n] =
                    LOG2E * bias[(bb+hh)*(N_*M_) + (n0+n)*M_ + m0 + mc];
            }
        }
        // --- delta_pos ---
#pragma unroll
        for (int it = 0; it < 12; it++) {
            int idx = it*128 + t;
            int n = idx / 48; int rem = idx - n*48;
            int mc = rem / 3; int c = rem - mc*3;
            sDPs[c*528 + mc*33 + n] = dp[((b*N_ + n0+n)*M_ + m0+mc)*3 + c];
        }
        // --- vw (gathered, duplicated) ---
        if (t < 64) {
            int mc = t >> 2, hh = t & 3;
            int m = m0 + mc;
            int r = (m < N_) ? m : oc[m - N_];
            float v = g_VW[(b*N_ + r)*H_ + h0 + hh];
            sVW[mc*4 + hh] = pk2(v, v);
        }
        __syncthreads();

        // --- compute ---
#pragma unroll
        for (int jj = 0; jj < 4; jj++) {
            int mc = s*4 + jj;
            ull kd[16];
            const ulonglong2* kp = (const ulonglong2*)&sK[h*260 + mc*16];
#pragma unroll
            for (int j8 = 0; j8 < 8; j8++) { ulonglong2 v = kp[j8]; kd[2*j8] = v.x; kd[2*j8+1] = v.y; }
            ull vw2 = sVW[mc*4 + h];
#pragma unroll
            for (int rp = 0; rp < 2; rp++) {
                int na = nq*4 + rp*2;
                ull l2 = pk2(sB[h*529 + mc*33 + na], sB[h*529 + mc*33 + na + 1]);
#pragma unroll
                for (int d = 0; d < 16; d++) l2 = fma2_(qpk[rp][d], kd[d], l2);
                float l0, l1; upk2(l0, l1, l2);
                ull p2 = pk2(ex2_(l0), ex2_(l1));
                den[rp] = add2_(den[rp], p2);
                ull pv = mul2_(p2, vw2);
#pragma unroll
                for (int c = 0; c < 3; c++) {
                    ull d2 = pk2(sDPs[c*528 + mc*33 + na], sDPs[c*528 + mc*33 + na + 1]);
                    Ac[rp][c] = fma2_(pv, d2, Ac[rp][c]);
                }
            }
        }
    }

    __syncthreads();
#pragma unroll
    for (int rp = 0; rp < 2; rp++) {
        int rpg = nq*2 + rp;
        float x0, x1;
        upk2(x0, x1, den[rp]);    scomb[s][h][rpg][0] = make_float2(x0, x1);
        upk2(x0, x1, Ac[rp][0]);  scomb[s][h][rpg][1] = make_float2(x0, x1);
        upk2(x0, x1, Ac[rp][1]);  scomb[s][h][rpg][2] = make_float2(x0, x1);
        upk2(x0, x1, Ac[rp][2]);  scomb[s][h][rpg][3] = make_float2(x0, x1);
    }
    __syncthreads();

    // reduce over s and write partials: slot = (hh, rowpair, val)
#pragma unroll
    for (int rep = 0; rep < 2; rep++) {
        int slot = rep*128 + t;
        int val = slot & 3, rp = (slot >> 2) & 15, hh = slot >> 6;
        float2 a = scomb[0][hh][rp][val];
#pragma unroll
        for (int ss = 1; ss < 4; ss++) {
            float2 q = scomb[ss][hh][rp][val];
            a.x += q.x; a.y += q.y;
        }
        int n = n0 + rp*2;
        int base = ((((g*2 + ms)*2 + b)*N_ + n)*4 + hh)*4 + val;
        g_part[base]      = a.x;
        g_part[base + 16] = a.y;   // next n row (+1): stride 16 floats per n
    }
}

// ---------------- kernel 5: final combine (sum over ms, heads; divide) ----------------
__global__ __launch_bounds__(256) void final_kernel(float* __restrict__ out)
{
    int i = blockIdx.x*256 + threadIdx.x;   // 4 blocks -> 1024 = B*N
    int b = i >> 9, n = i & 511;
    float f0 = 0.f, f1 = 0.f, f2 = 0.f;
#pragma unroll 4
    for (int g = 0; g < 12; g++) {
#pragma unroll
        for (int hh = 0; hh < 4; hh++) {
            float4 v0 = *(const float4*)&g_part[(((g*2+0)*2 + b)*N_ + n)*16 + hh*4];
            float4 v1 = *(const float4*)&g_part[(((g*2+1)*2 + b)*N_ + n)*16 + hh*4];
            float inv = 1.0f / (v0.x + v1.x);
            f0 = fmaf(v0.y + v1.y, inv, f0);
            f1 = fmaf(v0.z + v1.z, inv, f1);
            f2 = fmaf(v0.w + v1.w, inv, f2);
        }
    }
    out[i*3+0] = f0; out[i*3+1] = f1; out[i*3+2] = f2;
}

// ---------------- launch ----------------
extern "C" void kernel_launch(void* const* d_in, const int* in_sizes, int n_in,
                              void* d_out, int out_size)
{
    const float* query = (const float*)d_in[0];
    const float* bias  = (const float*)d_in[1];
    const float* dp    = (const float*)d_in[2];
    const int*   oc    = (const int*)  d_in[3];
    const float* Wq    = (const float*)d_in[4];
    const float* bq    = (const float*)d_in[5];
    const float* Wk    = (const float*)d_in[6];
    const float* bk    = (const float*)d_in[7];
    const float* Wv    = (const float*)d_in[8];
    const float* bv    = (const float*)d_in[9];
    const float* wf    = (const float*)d_in[10];
    float* out = (float*)d_out;

    wveff_kernel<<<H_, E_>>>(Wv, bv, wf);
    qk_gemm<<<dim3(24, 16), 128>>>(query, Wq, bq, Wk, bk);
    vw_kernel<<<B_*N_, E_>>>(query);
    attn_kernel<<<dim3(12, 16, 4), 128>>>(bias, dp, oc);
    final_kernel<<<4, 256>>>(out);
}

// round 5
// speedup vs baseline: 1.4411x; 1.0037x over previous
#include <cuda_runtime.h>

#define B_    2
#define N_    512
#define E_    768
#define H_    48
#define D_    16
#define NEXP_ 256
#define M_    768
#define LOG2E 1.4426950408889634f

typedef unsigned long long ull;

__device__ __forceinline__ ull pk2(float lo, float hi){ ull r; asm("mov.b64 %0,{%1,%2};":"=l"(r):"f"(lo),"f"(hi)); return r; }
__device__ __forceinline__ void upk2(float&lo,float&hi,ull v){ asm("mov.b64 {%0,%1},%2;":"=f"(lo),"=f"(hi):"l"(v)); }
__device__ __forceinline__ ull fma2_(ull a, ull b, ull c){ ull d; asm("fma.rn.f32x2 %0,%1,%2,%3;":"=l"(d):"l"(a),"l"(b),"l"(c)); return d; }
__device__ __forceinline__ ull add2_(ull a, ull b){ ull d; asm("add.rn.f32x2 %0,%1,%2;":"=l"(d):"l"(a),"l"(b)); return d; }
__device__ __forceinline__ ull mul2_(ull a, ull b){ ull d; asm("mul.rn.f32x2 %0,%1,%2;":"=l"(d):"l"(a),"l"(b)); return d; }
__device__ __forceinline__ float ex2_(float x){ float r; asm("ex2.approx.f32 %0,%1;":"=f"(r):"f"(x)); return r; }

// ---------------- device scratch ----------------
__device__ float g_Q[B_*N_*E_];          // Q proj, pre-scaled by 0.25*log2e
__device__ float g_K[B_*N_*E_];          // K proj
__device__ float g_VW[B_*N_*H_];         // v . w_force per head
__device__ float g_Wveff[H_*E_];
__device__ float g_beff[H_];
__device__ float g_part[12*2*B_*N_*16];  // [g][ms][b][n][hh][4]: den,A0,A1,A2

// ---------------- kernel 1: fold Wv with w_force ----------------
__global__ void wveff_kernel(const float* __restrict__ Wv,
                             const float* __restrict__ bv,
                             const float* __restrict__ wf)
{
    int h = blockIdx.x, e = threadIdx.x;
    float sv = 0.f;
#pragma unroll
    for (int dd = 0; dd < 16; dd++)
        sv = fmaf(wf[h*16+dd], Wv[(h*16+dd)*E_ + e], sv);
    g_Wveff[h*E_ + e] = sv;
    if (e == 0) {
        float bb = 0.f;
#pragma unroll
        for (int dd = 0; dd < 16; dd++)
            bb = fmaf(wf[h*16+dd], bv[h*16+dd], bb);
        g_beff[h] = bb;
    }
}

// ---------------- kernel 2: fused Q+K projection GEMM (f32x2) ----------------
// 64x64 tile, 128 threads, micro 4 rows x 8 cols (4 col-pairs as f32x2).
__global__ __launch_bounds__(128) void qk_gemm(
    const float* __restrict__ A,
    const float* __restrict__ Wq, const float* __restrict__ bq,
    const float* __restrict__ Wk, const float* __restrict__ bk)
{
    __shared__ ull   Asd[16*64];   // [k][row] duplicated (a,a)
    __shared__ float Bs[16*68];    // [k][col] padded

    int t  = threadIdx.x;
    int tx = t & 7, ty = t >> 3;          // tx: col group (8 cols), ty: row group (4 rows)
    int row0 = blockIdx.y * 64;
    int col0 = blockIdx.x * 64;

    const float* __restrict__ W; const float* __restrict__ bvec;
    float scale; float* C; int cb;
    if (col0 < E_) { W = Wq; bvec = bq; scale = 0.25f*LOG2E; C = g_Q; cb = col0; }
    else           { W = Wk; bvec = bk; scale = 1.0f;        C = g_K; cb = col0 - E_; }

    ull acc[4][4];
#pragma unroll
    for (int r = 0; r < 4; r++)
#pragma unroll
        for (int j = 0; j < 4; j++) acc[r][j] = 0ull;

    for (int k0 = 0; k0 < E_; k0 += 16) {
#pragma unroll
        for (int it = 0; it < 2; it++) {
            int idx = it*128 + t;
            int row = idx >> 2;         // 0..63
            int kq  = (idx & 3) * 4;    // k sub-offset
            float4 va = *(const float4*)(A + (row0+row)*E_ + k0 + kq);
            Asd[(kq+0)*64+row] = pk2(va.x, va.x);
            Asd[(kq+1)*64+row] = pk2(va.y, va.y);
            Asd[(kq+2)*64+row] = pk2(va.z, va.z);
            Asd[(kq+3)*64+row] = pk2(va.w, va.w);
            float4 vb = *(const float4*)(W + (cb+row)*E_ + k0 + kq);
            Bs[(kq+0)*68+row] = vb.x;
            Bs[(kq+1)*68+row] = vb.y;
            Bs[(kq+2)*68+row] = vb.z;
            Bs[(kq+3)*68+row] = vb.w;
        }
        __syncthreads();
#pragma unroll
        for (int k = 0; k < 16; k++) {
            ull a2[4];
#pragma unroll
            for (int r = 0; r < 4; r++) a2[r] = Asd[k*64 + ty*4 + r];
            const ull* bp = (const ull*)&Bs[k*68 + tx*8];
            ull b2[4];
            b2[0] = bp[0]; b2[1] = bp[1]; b2[2] = bp[2]; b2[3] = bp[3];
#pragma unroll
            for (int r = 0; r < 4; r++)
#pragma unroll
                for (int j = 0; j < 4; j++)
                    acc[r][j] = fma2_(a2[r], b2[j], acc[r][j]);
        }
        __syncthreads();
    }

    float bc[8];
#pragma unroll
    for (int j = 0; j < 8; j++) bc[j] = bvec[cb + tx*8 + j];
#pragma unroll
    for (int r = 0; r < 4; r++) {
        float* Cr = C + (row0 + ty*4 + r)*E_ + cb + tx*8;
        float4 o;
        float c0,c1;
        upk2(c0,c1,acc[r][0]); o.x = scale*(c0+bc[0]); o.y = scale*(c1+bc[1]);
        upk2(c0,c1,acc[r][1]); o.z = scale*(c0+bc[2]); o.w = scale*(c1+bc[3]);
        *(float4*)Cr = o;
        upk2(c0,c1,acc[r][2]); o.x = scale*(c0+bc[4]); o.y = scale*(c1+bc[5]);
        upk2(c0,c1,acc[r][3]); o.z = scale*(c0+bc[6]); o.w = scale*(c1+bc[7]);
        *(float4*)(Cr+4) = o;
    }
}

// ---------------- kernel 3: vw = query @ Wv_eff^T + b_eff ----------------
__global__ __launch_bounds__(768) void vw_kernel(const float* __restrict__ query)
{
    __shared__ float qrow[E_];
    int row = blockIdx.x;
    qrow[threadIdx.x] = query[row*E_ + threadIdx.x];
    __syncthreads();
    int h = threadIdx.x >> 4, lane = threadIdx.x & 15;
    const float* __restrict__ wv = &g_Wveff[h*E_];
    float sacc = 0.f;
#pragma unroll 8
    for (int j = lane; j < E_; j += 16) sacc = fmaf(qrow[j], wv[j], sacc);
#pragma unroll
    for (int o = 8; o > 0; o >>= 1) sacc += __shfl_down_sync(0xffffffffu, sacc, o, 16);
    if (lane == 0) g_VW[row*H_ + h] = sacc + g_beff[h];
}

// ---------------- kernel 4: fused attention (no-max softmax, f32x2) ----------------
// grid (12 hg, 16 ntile, b*2+ms).  128 threads: h=t&3, nq=(t>>2)&7, s=t>>5.
// Thread: 4 n-rows (2 packed row-pairs) x 4 m-cols per 16-chunk; 24 chunks (m-half).
__global__ __launch_bounds__(128) void attn_kernel(
    const float* __restrict__ bias, const float* __restrict__ dp,
    const int*   __restrict__ outcell)
{
    __shared__ ulonglong2 sKraw[4*130];        // h stride 260 ull (banks 0/8/16/24)
    __shared__ float  sB[4*529];               // h*529 + mc*33 + n : 32 distinct banks
    __shared__ float  sDPs[3*528];             // c*528 + mc*33 + n
    __shared__ ull    sVW[16*4];               // mc*4+h, duplicated
    __shared__ float2 scomb[4][4][16][4];      // [s][h][rowpair][val]

    ull* sK = (ull*)sKraw;

    int t  = threadIdx.x;
    int h  = t & 3;
    int nq = (t >> 2) & 7;
    int s  = t >> 5;
    int g  = blockIdx.x;
    int h0 = g * 4;
    int n0 = blockIdx.y * 32;
    int bz = blockIdx.z;
    int b  = bz >> 1, ms = bz & 1;
    const int* __restrict__ oc = outcell + b*NEXP_;

    // Q row-pairs, packed (row r, row r+1), invariant over m. Already *0.25*log2e.
    ull qpk[2][16];
#pragma unroll
    for (int rp = 0; rp < 2; rp++) {
        const float* q0 = &g_Q[(b*N_ + n0 + nq*4 + rp*2)*E_ + (h0+h)*D_];
        const float* q1 = q0 + E_;
#pragma unroll
        for (int d = 0; d < 16; d++) qpk[rp][d] = pk2(q0[d], q1[d]);
    }

    ull den[2] = {0ull, 0ull};
    ull Ac[2][3] = {{0ull,0ull,0ull},{0ull,0ull,0ull}};

#pragma unroll 1
    for (int ch = 0; ch < 24; ch++) {
        int m0 = ms*384 + ch*16;
        __syncthreads();
        // --- K (gathered, stored duplicated) ---
#pragma unroll
        for (int it = 0; it < 2; it++) {
            int idx = it*128 + t;
            int mc = idx >> 4, q4 = idx & 15;
            int hh = q4 >> 2, dg = (q4 & 3)*4;
            int m = m0 + mc;
            int r = (m < N_) ? m : oc[m - N_];
            float4 v = *(const float4*)&g_K[(b*N_ + r)*E_ + (h0+hh)*D_ + dg];
            ull* dst = &sK[hh*260 + mc*16 + dg];
            dst[0] = pk2(v.x,v.x); dst[1] = pk2(v.y,v.y);
            dst[2] = pk2(v.z,v.z); dst[3] = pk2(v.w,v.w);
        }
        // --- bias (scaled by log2e at stage time) ---
        {
            int bb = b*H_ + h0;
#pragma unroll
            for (int it = 0; it < 16; it++) {
                int idx = it*128 + t;
                int mc = idx & 15, n = (idx >> 4) & 31, hh = idx >> 9;
                sB[hh*529 + mc*33 + n] =
                    LOG2E * bias[(bb+hh)*(N_*M_) + (n0+n)*M_ + m0 + mc];
            }
        }
        // --- delta_pos ---
#pragma unroll
        for (int it = 0; it < 12; it++) {
            int idx = it*128 + t;
            int n = idx / 48; int rem = idx - n*48;
            int mc = rem / 3; int c = rem - mc*3;
            sDPs[c*528 + mc*33 + n] = dp[((b*N_ + n0+n)*M_ + m0+mc)*3 + c];
        }
        // --- vw (gathered, duplicated) ---
        if (t < 64) {
            int mc = t >> 2, hh = t & 3;
            int m = m0 + mc;
            int r = (m < N_) ? m : oc[m - N_];
            float v = g_VW[(b*N_ + r)*H_ + h0 + hh];
            sVW[mc*4 + hh] = pk2(v, v);
        }
        __syncthreads();

        // --- compute ---
#pragma unroll
        for (int jj = 0; jj < 4; jj++) {
            int mc = s*4 + jj;
            ull kd[16];
            const ulonglong2* kp = (const ulonglong2*)&sK[h*260 + mc*16];
#pragma unroll
            for (int j8 = 0; j8 < 8; j8++) { ulonglong2 v = kp[j8]; kd[2*j8] = v.x; kd[2*j8+1] = v.y; }
            ull vw2 = sVW[mc*4 + h];
#pragma unroll
            for (int rp = 0; rp < 2; rp++) {
                int na = nq*4 + rp*2;
                ull l2 = pk2(sB[h*529 + mc*33 + na], sB[h*529 + mc*33 + na + 1]);
#pragma unroll
                for (int d = 0; d < 16; d++) l2 = fma2_(qpk[rp][d], kd[d], l2);
                float l0, l1; upk2(l0, l1, l2);
                ull p2 = pk2(ex2_(l0), ex2_(l1));
                den[rp] = add2_(den[rp], p2);
                ull pv = mul2_(p2, vw2);
#pragma unroll
                for (int c = 0; c < 3; c++) {
                    ull d2 = pk2(sDPs[c*528 + mc*33 + na], sDPs[c*528 + mc*33 + na + 1]);
                    Ac[rp][c] = fma2_(pv, d2, Ac[rp][c]);
                }
            }
        }
    }

    __syncthreads();
#pragma unroll
    for (int rp = 0; rp < 2; rp++) {
        int rpg = nq*2 + rp;
        float x0, x1;
        upk2(x0, x1, den[rp]);    scomb[s][h][rpg][0] = make_float2(x0, x1);
        upk2(x0, x1, Ac[rp][0]);  scomb[s][h][rpg][1] = make_float2(x0, x1);
        upk2(x0, x1, Ac[rp][1]);  scomb[s][h][rpg][2] = make_float2(x0, x1);
        upk2(x0, x1, Ac[rp][2]);  scomb[s][h][rpg][3] = make_float2(x0, x1);
    }
    __syncthreads();

    // reduce over s and write partials: slot = (hh, rowpair, val)
#pragma unroll
    for (int rep = 0; rep < 2; rep++) {
        int slot = rep*128 + t;
        int val = slot & 3, rp = (slot >> 2) & 15, hh = slot >> 6;
        float2 a = scomb[0][hh][rp][val];
#pragma unroll
        for (int ss = 1; ss < 4; ss++) {
            float2 q = scomb[ss][hh][rp][val];
            a.x += q.x; a.y += q.y;
        }
        int n = n0 + rp*2;
        int base = ((((g*2 + ms)*2 + b)*N_ + n)*4 + hh)*4 + val;
        g_part[base]      = a.x;
        g_part[base + 16] = a.y;   // next n row (+1): stride 16 floats per n
    }
}

// ---------------- kernel 5: final combine (sum over ms, heads; divide) ----------------
__global__ __launch_bounds__(256) void final_kernel(float* __restrict__ out)
{
    int i = blockIdx.x*256 + threadIdx.x;   // 4 blocks -> 1024 = B*N
    int b = i >> 9, n = i & 511;
    float f0 = 0.f, f1 = 0.f, f2 = 0.f;
#pragma unroll 4
    for (int g = 0; g < 12; g++) {
#pragma unroll
        for (int hh = 0; hh < 4; hh++) {
            float4 v0 = *(const float4*)&g_part[(((g*2+0)*2 + b)*N_ + n)*16 + hh*4];
            float4 v1 = *(const float4*)&g_part[(((g*2+1)*2 + b)*N_ + n)*16 + hh*4];
            float inv = 1.0f / (v0.x + v1.x);
            f0 = fmaf(v0.y + v1.y, inv, f0);
            f1 = fmaf(v0.z + v1.z, inv, f1);
            f2 = fmaf(v0.w + v1.w, inv, f2);
        }
    }
    out[i*3+0] = f0; out[i*3+1] = f1; out[i*3+2] = f2;
}

// ---------------- launch ----------------
extern "C" void kernel_launch(void* const* d_in, const int* in_sizes, int n_in,
                              void* d_out, int out_size)
{
    const float* query = (const float*)d_in[0];
    const float* bias  = (const float*)d_in[1];
    const float* dp    = (const float*)d_in[2];
    const int*   oc    = (const int*)  d_in[3];
    const float* Wq    = (const float*)d_in[4];
    const float* bq    = (const float*)d_in[5];
    const float* Wk    = (const float*)d_in[6];
    const float* bk    = (const float*)d_in[7];
    const float* Wv    = (const float*)d_in[8];
    const float* bv    = (const float*)d_in[9];
    const float* wf    = (const float*)d_in[10];
    float* out = (float*)d_out;

    wveff_kernel<<<H_, E_>>>(Wv, bv, wf);
    qk_gemm<<<dim3(24, 16), 128>>>(query, Wq, bq, Wk, bk);
    vw_kernel<<<B_*N_, E_>>>(query);
    attn_kernel<<<dim3(12, 16, 4), 128>>>(bias, dp, oc);
    final_kernel<<<4, 256>>>(out);
}